// round 3
// baseline (speedup 1.0000x reference)
#include <cuda_runtime.h>
#include <math.h>

// Problem constants
#define NB 8
#define NC 512
#define ND 256
#define NT 2048

// ---------------- scratch (device globals; no allocations allowed) ----------
__device__ float g_theta[(size_t)NB * ND * NT];           // 16.8 MB
__device__ float g_phi  [(size_t)NB * ND * NT];           // 16.8 MB
__device__ float g_gv   [(size_t)NB * ND * NT];           // 16.8 MB
__device__ float g_W    [(size_t)NB * NT * NT];           // 134 MB
__device__ float g_attn [(size_t)NB * ND * NT];           // 16.8 MB
__device__ float g_h    [(size_t)NB * NC * NT];           // 33.5 MB
__device__ float g_mean [NC];
__device__ float g_istd [NC];

// ---------------- generic batched SGEMM: C = op(A) * B (+ bias[m]) ----------
// Tile 128x128, K-step 8, 256 threads, 8x8 micro-tile per thread.
// TRANS_A=false: A is (M,K) row-major, element A[m*lda + k]
// TRANS_A=true : A is (K,M) row-major, element A[k*lda + m]
// B is (K,N) row-major, C is (M,N) row-major. All dims multiples of tile sizes.
template <bool TRANS_A, bool ADD_BIAS>
__global__ __launch_bounds__(256, 2) void sgemm_kernel(
    const float* __restrict__ A, const float* __restrict__ Bm,
    float* __restrict__ C, const float* __restrict__ bias,
    int M, int N, int K, int lda, int ldb, int ldc,
    long long strideA, long long strideB, long long strideC)
{
    __shared__ float As[8][132];
    __shared__ float Bs[8][132];

    const int bz = blockIdx.z;
    A  += (long long)bz * strideA;
    Bm += (long long)bz * strideB;
    C  += (long long)bz * strideC;

    const int m0 = blockIdx.y * 128;
    const int n0 = blockIdx.x * 128;
    const int tid = threadIdx.x;
    const int tr = tid >> 4;   // 0..15 (row group)
    const int tc = tid & 15;   // 0..15 (col group)

    float acc[8][8];
#pragma unroll
    for (int i = 0; i < 8; i++)
#pragma unroll
        for (int j = 0; j < 8; j++) acc[i][j] = 0.f;

    for (int k0 = 0; k0 < K; k0 += 8) {
        // --- load A tile into As[kk][m] ---
        if (TRANS_A) {
#pragma unroll
            for (int r = 0; r < 4; r++) {
                int e = tid + r * 256;
                int kk = e >> 7, m = e & 127;
                As[kk][m] = A[(long long)(k0 + kk) * lda + (m0 + m)];
            }
        } else {
#pragma unroll
            for (int r = 0; r < 4; r++) {
                int e = tid + r * 256;
                int m = e >> 3, kk = e & 7;
                As[kk][m] = A[(long long)(m0 + m) * lda + (k0 + kk)];
            }
        }
        // --- load B tile into Bs[kk][n] (coalesced) ---
#pragma unroll
        for (int r = 0; r < 4; r++) {
            int e = tid + r * 256;
            int kk = e >> 7, n = e & 127;
            Bs[kk][n] = Bm[(long long)(k0 + kk) * ldb + (n0 + n)];
        }
        __syncthreads();

#pragma unroll
        for (int kk = 0; kk < 8; kk++) {
            float av[8], bv[8];
#pragma unroll
            for (int i = 0; i < 8; i++) av[i] = As[kk][tr * 8 + i];
#pragma unroll
            for (int j = 0; j < 8; j++) bv[j] = Bs[kk][tc * 8 + j];
#pragma unroll
            for (int i = 0; i < 8; i++)
#pragma unroll
                for (int j = 0; j < 8; j++)
                    acc[i][j] += av[i] * bv[j];
        }
        __syncthreads();
    }

#pragma unroll
    for (int i = 0; i < 8; i++) {
        const int m = m0 + tr * 8 + i;
        const float bb = ADD_BIAS ? bias[m] : 0.f;
        float* crow = C + (long long)m * ldc + n0 + tc * 8;
#pragma unroll
        for (int j = 0; j < 8; j++) crow[j] = acc[i][j] + bb;
    }
}

// ---------------- fused row softmax (in place), folds 1/Z into P ------------
// One block per row (B*T rows), 256 threads, 8 elems/thread in registers.
__global__ __launch_bounds__(256) void softmax_kernel(float* __restrict__ W)
{
    float* p = W + (size_t)blockIdx.x * NT;
    const int t = threadIdx.x;

    float x[8];
#pragma unroll
    for (int r = 0; r < 8; r++) x[r] = p[t + r * 256];

    float m = x[0];
#pragma unroll
    for (int r = 1; r < 8; r++) m = fmaxf(m, x[r]);
#pragma unroll
    for (int o = 16; o; o >>= 1) m = fmaxf(m, __shfl_xor_sync(0xffffffffu, m, o));

    __shared__ float smax[8], ssum[8];
    if ((t & 31) == 0) smax[t >> 5] = m;
    __syncthreads();
    m = smax[0];
#pragma unroll
    for (int i = 1; i < 8; i++) m = fmaxf(m, smax[i]);

    float e[8], s = 0.f;
#pragma unroll
    for (int r = 0; r < 8; r++) { e[r] = __expf(x[r] - m); s += e[r]; }
#pragma unroll
    for (int o = 16; o; o >>= 1) s += __shfl_xor_sync(0xffffffffu, s, o);
    if ((t & 31) == 0) ssum[t >> 5] = s;
    __syncthreads();
    s = ssum[0];
#pragma unroll
    for (int i = 1; i < 8; i++) s += ssum[i];

    const float inv = 1.f / s;
#pragma unroll
    for (int r = 0; r < 8; r++) p[t + r * 256] = e[r] * inv;
}

// ---------------- BatchNorm stats: per channel over (B, T) ------------------
__global__ __launch_bounds__(256) void bn_stats_kernel(
    const float* __restrict__ h, float* __restrict__ mean, float* __restrict__ istd)
{
    const int c = blockIdx.x;
    float s1 = 0.f, s2 = 0.f;
    for (int i = threadIdx.x; i < NB * NT; i += 256) {
        const int b = i >> 11, t = i & (NT - 1);
        const float v = h[(size_t)b * NC * NT + (size_t)c * NT + t];
        s1 += v; s2 += v * v;
    }
#pragma unroll
    for (int o = 16; o; o >>= 1) {
        s1 += __shfl_xor_sync(0xffffffffu, s1, o);
        s2 += __shfl_xor_sync(0xffffffffu, s2, o);
    }
    __shared__ float a1[8], a2[8];
    if ((threadIdx.x & 31) == 0) { a1[threadIdx.x >> 5] = s1; a2[threadIdx.x >> 5] = s2; }
    __syncthreads();
    if (threadIdx.x == 0) {
        float t1 = 0.f, t2 = 0.f;
#pragma unroll
        for (int i = 0; i < 8; i++) { t1 += a1[i]; t2 += a2[i]; }
        const float n = (float)(NB * NT);
        const float mu = t1 / n;
        const float var = t2 / n - mu * mu;
        mean[c] = mu;
        istd[c] = rsqrtf(var + 1e-5f);
    }
}

// ---------------- final: out = inpt + gamma*(h-mean)*istd + beta ------------
__global__ __launch_bounds__(256) void bn_apply_kernel(
    const float* __restrict__ inpt, const float* __restrict__ h,
    const float* __restrict__ gamma, const float* __restrict__ beta,
    const float* __restrict__ mean, const float* __restrict__ istd,
    float* __restrict__ out)
{
    const int i = blockIdx.x * 256 + threadIdx.x;   // total = 8*512*2048 = 8388608
    const int c = (i >> 11) & (NC - 1);
    out[i] = inpt[i] + gamma[c] * ((h[i] - mean[c]) * istd[c]) + beta[c];
}

// ---------------- launch -----------------------------------------------------
extern "C" void kernel_launch(void* const* d_in, const int* in_sizes, int n_in,
                              void* d_out, int out_size)
{
    const float* inpt    = (const float*)d_in[0];
    const float* theta_w = (const float*)d_in[1];
    const float* theta_b = (const float*)d_in[2];
    const float* phi_w   = (const float*)d_in[3];
    const float* phi_b   = (const float*)d_in[4];
    const float* gw      = (const float*)d_in[5];
    const float* gb      = (const float*)d_in[6];
    const float* ht_w    = (const float*)d_in[7];
    const float* ht_b    = (const float*)d_in[8];
    const float* bn_g    = (const float*)d_in[9];
    const float* bn_b    = (const float*)d_in[10];
    float* out = (float*)d_out;

    float *p_theta, *p_phi, *p_g, *p_W, *p_attn, *p_h, *p_mean, *p_istd;
    cudaGetSymbolAddress((void**)&p_theta, g_theta);
    cudaGetSymbolAddress((void**)&p_phi,   g_phi);
    cudaGetSymbolAddress((void**)&p_g,     g_gv);
    cudaGetSymbolAddress((void**)&p_W,     g_W);
    cudaGetSymbolAddress((void**)&p_attn,  g_attn);
    cudaGetSymbolAddress((void**)&p_h,     g_h);
    cudaGetSymbolAddress((void**)&p_mean,  g_mean);
    cudaGetSymbolAddress((void**)&p_istd,  g_istd);

    const long long sBD = (long long)ND * NT;      // per-batch (D,T)
    const long long sBC = (long long)NC * NT;      // per-batch (C,T)
    const long long sWW = (long long)NT * NT;      // per-batch (T,T)

    // 1) theta / phi / g : (D,C) x (C,T) + bias   [NN, M=256 N=2048 K=512]
    {
        dim3 grid(NT / 128, ND / 128, NB);
        sgemm_kernel<false, true><<<grid, 256>>>(theta_w, inpt, p_theta, theta_b,
            ND, NT, NC, NC, NT, NT, 0LL, sBC, sBD);
        sgemm_kernel<false, true><<<grid, 256>>>(phi_w, inpt, p_phi, phi_b,
            ND, NT, NC, NC, NT, NT, 0LL, sBC, sBD);
        sgemm_kernel<false, true><<<grid, 256>>>(gw, inpt, p_g, gb,
            ND, NT, NC, NC, NT, NT, 0LL, sBC, sBD);
    }

    // 2) W[t,s] = theta^T * phi  [TN, M=2048 N=2048 K=256]
    {
        dim3 grid(NT / 128, NT / 128, NB);
        sgemm_kernel<true, false><<<grid, 256>>>(p_theta, p_phi, p_W, nullptr,
            NT, NT, ND, NT, NT, NT, sBD, sBD, sWW);
    }

    // 3) softmax over s (in place, normalized)
    softmax_kernel<<<NB * NT, 256>>>(p_W);

    // 4) attn = g * P   [NN, M=256 N=2048 K=2048]
    {
        dim3 grid(NT / 128, ND / 128, NB);
        sgemm_kernel<false, false><<<grid, 256>>>(p_g, p_W, p_attn, nullptr,
            ND, NT, NT, NT, NT, NT, sBD, sWW, sBD);
    }

    // 5) h = ht_w * attn + ht_b   [NN, M=512 N=2048 K=256]
    {
        dim3 grid(NT / 128, NC / 128, NB);
        sgemm_kernel<false, true><<<grid, 256>>>(ht_w, p_attn, p_h, ht_b,
            NC, NT, ND, ND, NT, NT, 0LL, sBD, sBC);
    }

    // 6) BN stats + apply with residual
    bn_stats_kernel<<<NC, 256>>>(p_h, p_mean, p_istd);
    bn_apply_kernel<<<(NB * NC * NT) / 256, 256>>>(inpt, p_h, bn_g, bn_b,
                                                   p_mean, p_istd, out);
}

// round 6
// speedup vs baseline: 2.6969x; 2.6969x over previous
#include <cuda_runtime.h>
#include <cstdint>
#include <math.h>

#define NB 8
#define NC 512
#define ND 256
#define NT 2048

// ---------------- scratch (device globals; no allocations allowed) ----------
__device__ float g_thT [(size_t)NB * NT * ND];   // theta^T  (B,T,D)
__device__ float g_phT [(size_t)NB * NT * ND];   // phi^T    (B,T,D)
__device__ float g_g   [(size_t)NB * ND * NT];   // g        (B,D,T)
__device__ float g_W   [(size_t)NB * NT * NT];   // W / P    (B,T,S)
__device__ float g_atT [(size_t)NB * NT * ND];   // attn^T   (B,S,D)
__device__ float g_h   [(size_t)NB * NC * NT];   // h        (B,C,T)
__device__ float g_mean[NC];
__device__ float g_istd[NC];

// ---------------- helpers ----------------------------------------------------
__device__ __forceinline__ float t32(float x) {       // fp32 -> tf32 (RN)
    uint32_t u;
    asm("cvt.rn.tf32.f32 %0, %1;" : "=r"(u) : "f"(x));
    return __uint_as_float(u);
}

__device__ __forceinline__ void mma8(float* d, const uint32_t* a, const uint32_t* b) {
    asm volatile(
        "mma.sync.aligned.m16n8k8.row.col.f32.tf32.tf32.f32 "
        "{%0,%1,%2,%3}, {%4,%5,%6,%7}, {%8,%9}, {%0,%1,%2,%3};"
        : "+f"(d[0]), "+f"(d[1]), "+f"(d[2]), "+f"(d[3])
        : "r"(a[0]), "r"(a[1]), "r"(a[2]), "r"(a[3]), "r"(b[0]), "r"(b[1]));
}

// SMEM tile geometry (fragment-permuted storage)
// A: 32 slots (mf0..7 x ks0..3), each slot = 32 lanes * 4 floats, stride 132
// B: 64 slots (nf0..15 x ks0..3), each slot = 32 lanes * 2 floats, stride 68
#define A_SLOT 132
#define B_SLOT 68
#define A_FLOATS (32 * A_SLOT)            // 4224
#define B_FLOATS (64 * B_SLOT)            // 4352
#define BUF_FLOATS (A_FLOATS + B_FLOATS)  // 8576
static constexpr int SMEM_BYTES = 2 * BUF_FLOATS * 4;   // 68608

// ---------------- tf32 mma.sync batched GEMM ---------------------------------
// A natural (M,K) row-major.
// TB=false: B natural (N,K). TB=true: B is (K,N) (B[n][k] = Bg[k*ldb+n]).
// TOUT=false: C (M,N) ldc. TOUT=true: C[n*ldc + m]. Bias per-m.
template <bool TB, bool TOUT, bool BIAS>
__global__ __launch_bounds__(256, 2) void tgemm(
    const float* __restrict__ A, const float* __restrict__ B, float* __restrict__ C,
    const float* __restrict__ bias, int K, int lda, int ldb, int ldc,
    long long sA, long long sB, long long sC)
{
    extern __shared__ float sm[];
    const int tid = threadIdx.x;
    const int lane = tid & 31;
    const int wid = tid >> 5;
    const int warpM = wid >> 2, warpN = wid & 3;   // 2 x 4 warp grid
    const int g4 = lane >> 2, tig = lane & 3;      // mma lane decomposition
    const int bz = blockIdx.z;
    const int m0 = blockIdx.y * 128, n0 = blockIdx.x * 128;
    A += (long long)bz * sA;
    B += (long long)bz * sB;
    C += (long long)bz * sC;

    // writer decode (i adds 32 to w_row)
    const int w_row = tid >> 3;       // 0..31
    const int w_q   = tid & 7;        // float4 index along k (natural layouts)
    const int w_ks  = w_q >> 1, w_kh = w_q & 1;

    float acc[4][4][4];
#pragma unroll
    for (int a = 0; a < 4; a++)
#pragma unroll
        for (int b = 0; b < 4; b++)
#pragma unroll
            for (int c = 0; c < 4; c++) acc[a][b][c] = 0.f;

    const int nch = K >> 5;
    float4 pa[4];
    float4 pb[4];
    float  pbt[16];

    // ---- global loads into registers ----
    auto ldgA = [&](int ch) {
        const float* Ag = A + (size_t)m0 * lda + ch * 32 + w_q * 4;
#pragma unroll
        for (int i = 0; i < 4; i++)
            pa[i] = *(const float4*)(Ag + (size_t)(w_row + i * 32) * lda);
    };
    auto ldgB = [&](int ch) {
        if (TB) {
            const float* Bg = B + (size_t)(ch * 32) * ldb + n0 + (tid & 127);
            const int kq0 = tid >> 7;          // 0..1
#pragma unroll
            for (int i = 0; i < 4; i++) {
                const float* p = Bg + (size_t)((kq0 + 2 * i) * 4) * ldb;
                pbt[i * 4 + 0] = p[0];
                pbt[i * 4 + 1] = p[(size_t)ldb];
                pbt[i * 4 + 2] = p[2 * (size_t)ldb];
                pbt[i * 4 + 3] = p[3 * (size_t)ldb];
            }
        } else {
            const float* Bg = B + (size_t)n0 * ldb + ch * 32 + w_q * 4;
#pragma unroll
            for (int i = 0; i < 4; i++)
                pb[i] = *(const float4*)(Bg + (size_t)(w_row + i * 32) * ldb);
        }
    };

    // ---- registers -> permuted SMEM (with tf32 rounding) ----
    auto stsTile = [&](int buf) {
        float* smA = sm + buf * BUF_FLOATS;
        float* smB = smA + A_FLOATS;
#pragma unroll
        for (int i = 0; i < 4; i++) {
            const int row = w_row + i * 32;
            const int mf = row >> 4, g = row & 7, half = (row >> 3) & 1;
            const int base = (mf * 4 + w_ks) * A_SLOT + g * 16 + half + 2 * w_kh;
            smA[base + 0]  = t32(pa[i].x);
            smA[base + 4]  = t32(pa[i].y);
            smA[base + 8]  = t32(pa[i].z);
            smA[base + 12] = t32(pa[i].w);
        }
        if (TB) {
            const int n = tid & 127;
            const int nf = n >> 3, g = n & 7;
            const int kq0 = tid >> 7;
#pragma unroll
            for (int i = 0; i < 4; i++) {
                const int kq = kq0 + 2 * i;
                const int ks = kq >> 1, kh = kq & 1;
                const int base = (nf * 4 + ks) * B_SLOT + g * 8 + kh;
                smB[base + 0] = t32(pbt[i * 4 + 0]);
                smB[base + 2] = t32(pbt[i * 4 + 1]);
                smB[base + 4] = t32(pbt[i * 4 + 2]);
                smB[base + 6] = t32(pbt[i * 4 + 3]);
            }
        } else {
#pragma unroll
            for (int i = 0; i < 4; i++) {
                const int row = w_row + i * 32;
                const int nf = row >> 3, g = row & 7;
                const int base = (nf * 4 + w_ks) * B_SLOT + g * 8 + w_kh;
                smB[base + 0] = t32(pb[i].x);
                smB[base + 2] = t32(pb[i].y);
                smB[base + 4] = t32(pb[i].z);
                smB[base + 6] = t32(pb[i].w);
            }
        }
    };

    // ---- mainloop compute on one buffer ----
    auto compute = [&](int buf) {
        const float* smA = sm + buf * BUF_FLOATS;
        const float* smB = smA + A_FLOATS;
#pragma unroll
        for (int ks = 0; ks < 4; ks++) {
            uint32_t af[4][4], bf[4][2];
#pragma unroll
            for (int mf = 0; mf < 4; mf++) {
                const float4 v = *(const float4*)(smA + ((warpM * 4 + mf) * 4 + ks) * A_SLOT + lane * 4);
                af[mf][0] = __float_as_uint(v.x);
                af[mf][1] = __float_as_uint(v.y);
                af[mf][2] = __float_as_uint(v.z);
                af[mf][3] = __float_as_uint(v.w);
            }
#pragma unroll
            for (int nf = 0; nf < 4; nf++) {
                const float2 v = *(const float2*)(smB + ((warpN * 4 + nf) * 4 + ks) * B_SLOT + lane * 2);
                bf[nf][0] = __float_as_uint(v.x);
                bf[nf][1] = __float_as_uint(v.y);
            }
#pragma unroll
            for (int mf = 0; mf < 4; mf++)
#pragma unroll
                for (int nf = 0; nf < 4; nf++)
                    mma8(acc[mf][nf], af[mf], bf[nf]);
        }
    };

    // ---- pipelined loop ----
    ldgA(0); ldgB(0);
    stsTile(0);
    __syncthreads();
    for (int ch = 0; ch < nch; ch++) {
        if (ch + 1 < nch) { ldgA(ch + 1); ldgB(ch + 1); }
        compute(ch & 1);
        __syncthreads();
        if (ch + 1 < nch) {
            stsTile((ch + 1) & 1);
            __syncthreads();
        }
    }

    // ---- epilogue: direct stores (all touched 32B sectors fully covered) ----
#pragma unroll
    for (int mf = 0; mf < 4; mf++) {
        const int m = m0 + warpM * 64 + mf * 16 + g4;
        const float bv0 = BIAS ? bias[m] : 0.f;
        const float bv1 = BIAS ? bias[m + 8] : 0.f;
#pragma unroll
        for (int nf = 0; nf < 4; nf++) {
            const int n = n0 + warpN * 32 + nf * 8 + 2 * tig;
            if (TOUT) {
                C[(size_t)n * ldc + m]           = acc[mf][nf][0] + bv0;
                C[(size_t)(n + 1) * ldc + m]     = acc[mf][nf][1] + bv0;
                C[(size_t)n * ldc + m + 8]       = acc[mf][nf][2] + bv1;
                C[(size_t)(n + 1) * ldc + m + 8] = acc[mf][nf][3] + bv1;
            } else {
                *(float2*)(C + (size_t)m * ldc + n) =
                    make_float2(acc[mf][nf][0] + bv0, acc[mf][nf][1] + bv0);
                *(float2*)(C + (size_t)(m + 8) * ldc + n) =
                    make_float2(acc[mf][nf][2] + bv1, acc[mf][nf][3] + bv1);
            }
        }
    }
}

// ---------------- softmax (in place over rows of W) --------------------------
__global__ __launch_bounds__(256) void softmax_kernel(float* __restrict__ W)
{
    float* p = W + (size_t)blockIdx.x * NT;
    const int t = threadIdx.x;
    float x[8];
#pragma unroll
    for (int r = 0; r < 8; r++) x[r] = p[t + r * 256];
    float m = x[0];
#pragma unroll
    for (int r = 1; r < 8; r++) m = fmaxf(m, x[r]);
#pragma unroll
    for (int o = 16; o; o >>= 1) m = fmaxf(m, __shfl_xor_sync(0xffffffffu, m, o));
    __shared__ float smax[8], ssum[8];
    if ((t & 31) == 0) smax[t >> 5] = m;
    __syncthreads();
    m = smax[0];
#pragma unroll
    for (int i = 1; i < 8; i++) m = fmaxf(m, smax[i]);
    float e[8], s = 0.f;
#pragma unroll
    for (int r = 0; r < 8; r++) { e[r] = __expf(x[r] - m); s += e[r]; }
#pragma unroll
    for (int o = 16; o; o >>= 1) s += __shfl_xor_sync(0xffffffffu, s, o);
    if ((t & 31) == 0) ssum[t >> 5] = s;
    __syncthreads();
    s = ssum[0];
#pragma unroll
    for (int i = 1; i < 8; i++) s += ssum[i];
    const float inv = 1.f / s;
#pragma unroll
    for (int r = 0; r < 8; r++) p[t + r * 256] = e[r] * inv;
}

// ---------------- BatchNorm stats + apply ------------------------------------
__global__ __launch_bounds__(256) void bn_stats_kernel(
    const float* __restrict__ h, float* __restrict__ mean, float* __restrict__ istd)
{
    const int c = blockIdx.x;
    float s1 = 0.f, s2 = 0.f;
    for (int i = threadIdx.x; i < NB * NT; i += 256) {
        const int b = i >> 11, t = i & (NT - 1);
        const float v = h[(size_t)b * NC * NT + (size_t)c * NT + t];
        s1 += v; s2 += v * v;
    }
#pragma unroll
    for (int o = 16; o; o >>= 1) {
        s1 += __shfl_xor_sync(0xffffffffu, s1, o);
        s2 += __shfl_xor_sync(0xffffffffu, s2, o);
    }
    __shared__ float a1[8], a2[8];
    if ((threadIdx.x & 31) == 0) { a1[threadIdx.x >> 5] = s1; a2[threadIdx.x >> 5] = s2; }
    __syncthreads();
    if (threadIdx.x == 0) {
        float t1 = 0.f, t2 = 0.f;
#pragma unroll
        for (int i = 0; i < 8; i++) { t1 += a1[i]; t2 += a2[i]; }
        const float n = (float)(NB * NT);
        const float mu = t1 / n;
        const float var = t2 / n - mu * mu;
        mean[c] = mu;
        istd[c] = rsqrtf(var + 1e-5f);
    }
}

__global__ __launch_bounds__(256) void bn_apply_kernel(
    const float* __restrict__ inpt, const float* __restrict__ h,
    const float* __restrict__ gamma, const float* __restrict__ beta,
    const float* __restrict__ mean, const float* __restrict__ istd,
    float* __restrict__ out)
{
    const int i = blockIdx.x * 256 + threadIdx.x;
    const int c = (i >> 11) & (NC - 1);
    out[i] = inpt[i] + gamma[c] * ((h[i] - mean[c]) * istd[c]) + beta[c];
}

// ---------------- launch -----------------------------------------------------
extern "C" void kernel_launch(void* const* d_in, const int* in_sizes, int n_in,
                              void* d_out, int out_size)
{
    const float* inpt    = (const float*)d_in[0];
    const float* theta_w = (const float*)d_in[1];
    const float* theta_b = (const float*)d_in[2];
    const float* phi_w   = (const float*)d_in[3];
    const float* phi_b   = (const float*)d_in[4];
    const float* gw      = (const float*)d_in[5];
    const float* gb      = (const float*)d_in[6];
    const float* ht_w    = (const float*)d_in[7];
    const float* ht_b    = (const float*)d_in[8];
    const float* bn_g    = (const float*)d_in[9];
    const float* bn_b    = (const float*)d_in[10];
    float* out = (float*)d_out;

    float *p_thT, *p_phT, *p_g, *p_W, *p_atT, *p_h, *p_mean, *p_istd;
    cudaGetSymbolAddress((void**)&p_thT, g_thT);
    cudaGetSymbolAddress((void**)&p_phT, g_phT);
    cudaGetSymbolAddress((void**)&p_g,   g_g);
    cudaGetSymbolAddress((void**)&p_W,   g_W);
    cudaGetSymbolAddress((void**)&p_atT, g_atT);
    cudaGetSymbolAddress((void**)&p_h,   g_h);
    cudaGetSymbolAddress((void**)&p_mean, g_mean);
    cudaGetSymbolAddress((void**)&p_istd, g_istd);

    cudaFuncSetAttribute(tgemm<true,  true,  true >, cudaFuncAttributeMaxDynamicSharedMemorySize, SMEM_BYTES);
    cudaFuncSetAttribute(tgemm<true,  false, true >, cudaFuncAttributeMaxDynamicSharedMemorySize, SMEM_BYTES);
    cudaFuncSetAttribute(tgemm<false, false, false>, cudaFuncAttributeMaxDynamicSharedMemorySize, SMEM_BYTES);
    cudaFuncSetAttribute(tgemm<true,  true,  false>, cudaFuncAttributeMaxDynamicSharedMemorySize, SMEM_BYTES);
    cudaFuncSetAttribute(tgemm<false, false, true >, cudaFuncAttributeMaxDynamicSharedMemorySize, SMEM_BYTES);

    const long long sTD = (long long)NT * ND;
    const long long sDT = (long long)ND * NT;
    const long long sCT = (long long)NC * NT;
    const long long sTT = (long long)NT * NT;

    // 1) theta^T, phi^T : M=D, N=T, K=C; A=weight natural, B=inpt (K,N), OUT transposed (T,D)
    {
        dim3 grid(NT / 128, ND / 128, NB);
        tgemm<true, true, true><<<grid, 256, SMEM_BYTES>>>(theta_w, inpt, p_thT, theta_b,
            NC, NC, NT, ND, 0LL, sCT, sTD);
        tgemm<true, true, true><<<grid, 256, SMEM_BYTES>>>(phi_w, inpt, p_phT, phi_b,
            NC, NC, NT, ND, 0LL, sCT, sTD);
        tgemm<true, false, true><<<grid, 256, SMEM_BYTES>>>(gw, inpt, p_g, gb,
            NC, NC, NT, NT, 0LL, sCT, sDT);
    }

    // 2) W = thT x phT^T : M=N=T, K=D; both natural, OUT natural (T,S)
    {
        dim3 grid(NT / 128, NT / 128, NB);
        tgemm<false, false, false><<<grid, 256, SMEM_BYTES>>>(p_thT, p_phT, p_W, nullptr,
            ND, ND, ND, NT, sTD, sTD, sTT);
    }

    // 3) softmax rows of W
    softmax_kernel<<<NB * NT, 256>>>(p_W);

    // 4) attn^T = (g x P)^T : M=D, N=S, K=T; A=g natural, B=P (K,N), OUT transposed (S,D)
    {
        dim3 grid(NT / 128, ND / 128, NB);
        tgemm<true, true, false><<<grid, 256, SMEM_BYTES>>>(p_g, p_W, p_atT, nullptr,
            NT, NT, NT, ND, sDT, sTT, sTD);
    }

    // 5) h = ht_w x attn : M=C, N=T, K=D; A natural, B=attn^T natural (T,D), OUT natural (C,T)
    {
        dim3 grid(NT / 128, NC / 128, NB);
        tgemm<false, false, true><<<grid, 256, SMEM_BYTES>>>(ht_w, p_atT, p_h, ht_b,
            ND, ND, ND, NT, 0LL, sTD, sCT);
    }

    // 6) BN stats + apply with residual
    bn_stats_kernel<<<NC, 256>>>(p_h, p_mean, p_istd);
    bn_apply_kernel<<<(NB * NC * NT) / 256, 256>>>(inpt, p_h, bn_g, bn_b,
                                                   p_mean, p_istd, out);
}